// round 1
// baseline (speedup 1.0000x reference)
#include <cuda_runtime.h>
#include <math.h>

#define N_NODES 100000
#define N_EDGES 3200000
#define NP1     100001
#define NSCAN_BLOCKS 98   // ceil(100001/1024)

// ---------------- device scratch (static: no allocation allowed) ----------------
__device__ int   g_rowptr[NP1];
__device__ int   g_bsum[128];
__device__ int   g_pos[N_NODES];
__device__ int   g_ecol[N_EDGES];
__device__ float g_eval[N_EDGES];
__device__ float g_h0[(size_t)N_NODES * 128];
__device__ float g_h1[(size_t)N_NODES * 128];
__device__ float g_sup[(size_t)N_NODES * 256];   // [support | self] per row

// ---------------- CSR build ----------------
__global__ void k_zero_rowptr() {
    int i = blockIdx.x * blockDim.x + threadIdx.x;
    if (i < NP1) g_rowptr[i] = 0;
}

__global__ void k_hist(const int* __restrict__ rows) {
    int e = blockIdx.x * blockDim.x + threadIdx.x;
    if (e < N_EDGES) atomicAdd(&g_rowptr[rows[e] + 1], 1);
}

__global__ void k_scan1() {
    __shared__ int s[1024];
    int t = threadIdx.x;
    int i = blockIdx.x * 1024 + t;
    int v = (i < NP1) ? g_rowptr[i] : 0;
    s[t] = v;
    __syncthreads();
    #pragma unroll
    for (int off = 1; off < 1024; off <<= 1) {
        int tv = 0;
        if (t >= off) tv = s[t - off];
        __syncthreads();
        s[t] += tv;
        __syncthreads();
    }
    if (i < NP1) g_rowptr[i] = s[t];
    if (t == 1023) g_bsum[blockIdx.x] = s[1023];
}

__global__ void k_scan2() {
    // single thread: 98 partial sums
    int acc = 0;
    for (int b = 0; b < NSCAN_BLOCKS; b++) {
        acc += g_bsum[b];
        g_bsum[b] = acc;
    }
}

__global__ void k_scan3() {
    int b = blockIdx.x;
    if (b == 0) return;
    int i = b * 1024 + threadIdx.x;
    if (i < NP1) g_rowptr[i] += g_bsum[b - 1];
}

__global__ void k_copy_pos() {
    int i = blockIdx.x * blockDim.x + threadIdx.x;
    if (i < N_NODES) g_pos[i] = g_rowptr[i];
}

__global__ void k_fill(const int* __restrict__ rows, const int* __restrict__ cols,
                       const float* __restrict__ vals) {
    int e = blockIdx.x * blockDim.x + threadIdx.x;
    if (e >= N_EDGES) return;
    int r = rows[e];
    int p = atomicAdd(&g_pos[r], 1);
    g_ecol[p] = cols[e];
    g_eval[p] = vals[e];
}

// ---------------- GEMM: Y[:, :out1+out2] = act(X @ [W1|W2] (+bias)) ----------------
// X: [N,128] row-major. W (in,out) layout unless FLAG_TRANS (then W1 is (out,in)).
// Tile: 64 rows x 64 cols per block. 256 threads, warp = 8 rows, lane = 2 cols.
#define FLAG_TRANS    1
#define FLAG_BIASRELU 2
#define WS_STRIDE 66
#define GEMM_SMEM ((64*128 + 128*WS_STRIDE) * 4)

__global__ __launch_bounds__(256) void k_gemm(
    const float* __restrict__ X,
    const float* __restrict__ W1, const float* __restrict__ W2,
    int out1, int out2,
    const float* __restrict__ bias,
    float* __restrict__ Y, int ldy, int flags)
{
    extern __shared__ float sm[];
    float* xs = sm;                 // [64][128]
    float* ws = sm + 64 * 128;      // [128][WS_STRIDE], valid cols [0,64)

    const int row0 = blockIdx.x * 64;
    const int co0  = blockIdx.y * 64;
    const int tid  = threadIdx.x;

    // load X tile (float4, coalesced)
    const float4 zero4 = make_float4(0.f, 0.f, 0.f, 0.f);
    #pragma unroll
    for (int i = tid; i < 64 * 32; i += 256) {
        int r = i >> 5;         // row within tile
        int k4 = i & 31;        // float4 index within row
        float4 v = zero4;
        int row = row0 + r;
        if (row < N_NODES) v = *(const float4*)&X[(size_t)row * 128 + k4 * 4];
        ((float4*)xs)[r * 32 + k4] = v;
    }

    // load W tile into ws[k*WS_STRIDE + o]
    if (flags & FLAG_TRANS) {
        // W1 is (out,in): read coalesced over k
        for (int i = tid; i < 64 * 128; i += 256) {
            int o = i >> 7, k = i & 127;
            ws[k * WS_STRIDE + o] = W1[(size_t)(co0 + o) * 128 + k];
        }
    } else {
        // (in,out): read coalesced over o
        for (int i = tid; i < 64 * 128; i += 256) {
            int k = i >> 6, o = i & 63;
            int og = co0 + o;
            float v = (og < out1) ? W1[(size_t)k * out1 + og]
                                  : W2[(size_t)k * out2 + (og - out1)];
            ws[k * WS_STRIDE + o] = v;
        }
    }
    __syncthreads();

    const int warp = tid >> 5, lane = tid & 31;
    float acc[8][2];
    #pragma unroll
    for (int r = 0; r < 8; r++) { acc[r][0] = 0.f; acc[r][1] = 0.f; }

    const float* xrow = xs + warp * 8 * 128;
    const int oc = lane * 2;

    #pragma unroll 4
    for (int k0 = 0; k0 < 128; k0 += 4) {
        float2 w0 = *(const float2*)&ws[(k0 + 0) * WS_STRIDE + oc];
        float2 w1 = *(const float2*)&ws[(k0 + 1) * WS_STRIDE + oc];
        float2 w2 = *(const float2*)&ws[(k0 + 2) * WS_STRIDE + oc];
        float2 w3 = *(const float2*)&ws[(k0 + 3) * WS_STRIDE + oc];
        #pragma unroll
        for (int r = 0; r < 8; r++) {
            float4 xv = *(const float4*)&xrow[r * 128 + k0];
            acc[r][0] = fmaf(xv.x, w0.x, acc[r][0]);
            acc[r][0] = fmaf(xv.y, w1.x, acc[r][0]);
            acc[r][0] = fmaf(xv.z, w2.x, acc[r][0]);
            acc[r][0] = fmaf(xv.w, w3.x, acc[r][0]);
            acc[r][1] = fmaf(xv.x, w0.y, acc[r][1]);
            acc[r][1] = fmaf(xv.y, w1.y, acc[r][1]);
            acc[r][1] = fmaf(xv.z, w2.y, acc[r][1]);
            acc[r][1] = fmaf(xv.w, w3.y, acc[r][1]);
        }
    }

    // epilogue
    float b0 = 0.f, b1 = 0.f;
    if (flags & FLAG_BIASRELU) {
        b0 = bias[co0 + oc];
        b1 = bias[co0 + oc + 1];
    }
    #pragma unroll
    for (int r = 0; r < 8; r++) {
        int row = row0 + warp * 8 + r;
        if (row >= N_NODES) continue;
        float v0 = acc[r][0], v1 = acc[r][1];
        if (flags & FLAG_BIASRELU) {
            v0 = fmaxf(v0 + b0, 0.f);
            v1 = fmaxf(v1 + b1, 0.f);
        }
        float2 st; st.x = v0; st.y = v1;
        *(float2*)&Y[(size_t)row * ldy + co0 + oc] = st;
    }
}

// ---------------- LayerNorm (torch-style: ddof=1, gamma*(x-mean)/(std+eps)+beta) ----------------
__global__ __launch_bounds__(256) void k_ln(const float* __restrict__ in,
                                            float* __restrict__ out,
                                            const float* __restrict__ g,
                                            const float* __restrict__ b)
{
    int row  = blockIdx.x * 8 + (threadIdx.x >> 5);
    int lane = threadIdx.x & 31;
    float4 v = *(const float4*)&in[(size_t)row * 128 + lane * 4];
    float s = v.x + v.y + v.z + v.w;
    #pragma unroll
    for (int o = 16; o; o >>= 1) s += __shfl_xor_sync(0xffffffffu, s, o);
    float mean = s * (1.f / 128.f);
    float dx = v.x - mean, dy = v.y - mean, dz = v.z - mean, dw = v.w - mean;
    float ss = dx * dx + dy * dy + dz * dz + dw * dw;
    #pragma unroll
    for (int o = 16; o; o >>= 1) ss += __shfl_xor_sync(0xffffffffu, ss, o);
    float stdv = sqrtf(ss * (1.f / 127.f));
    float inv = 1.f / (stdv + 1e-6f);
    float4 gg = *(const float4*)&g[lane * 4];
    float4 bb = *(const float4*)&b[lane * 4];
    float4 o4;
    o4.x = gg.x * dx * inv + bb.x;
    o4.y = gg.y * dy * inv + bb.y;
    o4.z = gg.z * dz * inv + bb.z;
    o4.w = gg.w * dw * inv + bb.w;
    *(float4*)&out[(size_t)row * 128 + lane * 4] = o4;
}

// ---------------- GCN aggregate: out = relu(self + bias + sum_e val*sup[col]) ----------------
// sup layout: [N, 2*OUT], support at cols [0,OUT), self at [OUT, 2*OUT)
template <int OUT>
__global__ __launch_bounds__(256) void k_agg(const float* __restrict__ sup,
                                             const float* __restrict__ bias,
                                             float* __restrict__ out)
{
    const int LD = 2 * OUT;
    const int V = OUT / 32;
    int node = blockIdx.x * 8 + (threadIdx.x >> 5);
    int lane = threadIdx.x & 31;

    float acc[V];
    {
        const float* selfrow = sup + (size_t)node * LD + OUT + lane * V;
        #pragma unroll
        for (int i = 0; i < V; i++) acc[i] = selfrow[i] + bias[lane * V + i];
    }

    int e0 = g_rowptr[node], e1 = g_rowptr[node + 1];
    for (int eb = e0; eb < e1; eb += 32) {
        int rem = e1 - eb;
        int c = 0; float wv = 0.f;
        if (lane < rem) { c = g_ecol[eb + lane]; wv = g_eval[eb + lane]; }
        int n = rem < 32 ? rem : 32;
        for (int j = 0; j < n; j++) {
            int   cj = __shfl_sync(0xffffffffu, c, j);
            float wj = __shfl_sync(0xffffffffu, wv, j);
            const float* srow = sup + (size_t)cj * LD + lane * V;
            if (V == 4) {
                float4 sv = *(const float4*)srow;
                acc[0] = fmaf(wj, sv.x, acc[0]);
                acc[1] = fmaf(wj, sv.y, acc[1]);
                acc[2] = fmaf(wj, sv.z, acc[2]);
                acc[3] = fmaf(wj, sv.w, acc[3]);
            } else {
                float2 sv = *(const float2*)srow;
                acc[0] = fmaf(wj, sv.x, acc[0]);
                acc[1] = fmaf(wj, sv.y, acc[1]);
            }
        }
    }

    float* orow = out + (size_t)node * OUT + lane * V;
    #pragma unroll
    for (int i = 0; i < V; i++) orow[i] = fmaxf(acc[i], 0.f);
}

// ---------------- launch ----------------
extern "C" void kernel_launch(void* const* d_in, const int* in_sizes, int n_in,
                              void* d_out, int out_size)
{
    const float* x    = (const float*)d_in[0];
    const int*   er   = (const int*)d_in[1];
    const int*   ec   = (const int*)d_in[2];
    const float* ev   = (const float*)d_in[3];
    const float* fc1w = (const float*)d_in[4];
    const float* fc1b = (const float*)d_in[5];
    const float* fc2w = (const float*)d_in[6];
    const float* fc2b = (const float*)d_in[7];
    const float* lng  = (const float*)d_in[8];
    const float* lnb  = (const float*)d_in[9];
    const float* wn[4], *wsf[4], *gb[4];
    for (int i = 0; i < 4; i++) {
        wn[i]  = (const float*)d_in[10 + 3 * i];
        wsf[i] = (const float*)d_in[11 + 3 * i];
        gb[i]  = (const float*)d_in[12 + 3 * i];
    }
    float* outp = (float*)d_out;

    // resolve device scratch addresses (host-side query, capture-safe)
    float *h0, *h1, *sup;
    cudaGetSymbolAddress((void**)&h0,  g_h0);
    cudaGetSymbolAddress((void**)&h1,  g_h1);
    cudaGetSymbolAddress((void**)&sup, g_sup);

    cudaFuncSetAttribute(k_gemm, cudaFuncAttributeMaxDynamicSharedMemorySize, GEMM_SMEM);

    // ---- CSR build (amortized over 4 GCN layers) ----
    k_zero_rowptr<<<(NP1 + 255) / 256, 256>>>();
    k_hist<<<(N_EDGES + 255) / 256, 256>>>(er);
    k_scan1<<<NSCAN_BLOCKS, 1024>>>();
    k_scan2<<<1, 1>>>();
    k_scan3<<<NSCAN_BLOCKS, 1024>>>();
    k_copy_pos<<<(N_NODES + 255) / 256, 256>>>();
    k_fill<<<(N_EDGES + 255) / 256, 256>>>(er, ec, ev);

    const int RB = (N_NODES + 63) / 64;   // 1563

    // ---- fc1: relu(x @ fc1_w.T + b) -> h0 ----
    k_gemm<<<dim3(RB, 2), 256, GEMM_SMEM>>>(x, fc1w, nullptr, 128, 0, fc1b,
                                            h0, 128, FLAG_TRANS | FLAG_BIASRELU);
    // ---- fc2 -> h1 ----
    k_gemm<<<dim3(RB, 2), 256, GEMM_SMEM>>>(h0, fc2w, nullptr, 128, 0, fc2b,
                                            h1, 128, FLAG_TRANS | FLAG_BIASRELU);
    // ---- layernorm h1 -> h0 ----
    k_ln<<<N_NODES / 8, 256>>>(h1, h0, lng, lnb);

    // ---- GCN layers 1..3 (128 -> 128) ----
    float* cur = h0;
    float* nxt = h1;
    for (int l = 0; l < 3; l++) {
        k_gemm<<<dim3(RB, 4), 256, GEMM_SMEM>>>(cur, wn[l], wsf[l], 128, 128,
                                                nullptr, sup, 256, 0);
        k_agg<128><<<N_NODES / 8, 256>>>(sup, gb[l], nxt);
        float* t = cur; cur = nxt; nxt = t;
    }

    // ---- GCN layer 4 (128 -> 64) ----
    k_gemm<<<dim3(RB, 2), 256, GEMM_SMEM>>>(cur, wn[3], wsf[3], 64, 64,
                                            nullptr, sup, 128, 0);
    k_agg<64><<<N_NODES / 8, 256>>>(sup, gb[3], outp);
}

// round 3
// speedup vs baseline: 1.0427x; 1.0427x over previous
#include <cuda_runtime.h>
#include <cuda_bf16.h>
#include <cuda_fp16.h>
#include <mma.h>
#include <math.h>
#include <stdint.h>

using namespace nvcuda;

#define N_NODES 100000
#define N_EDGES 3200000
#define NP1     100001
#define NSCAN_BLOCKS 98

#define LDAB 264   // bf16 elems per smem row: [hi 0..127 | lo 128..255 | pad]
#define LDC  132   // f32 elems per row (same 528 bytes)

// ======================= device scratch =======================
__device__ int    g_rowptr[NP1];
__device__ int    g_bsum[128];
__device__ int    g_pos[N_NODES];
__device__ int    g_ecol[N_EDGES];
__device__ float  g_eval[N_EDGES];
__device__ float  g_h0[(size_t)N_NODES * 128];
__device__ float  g_h1[(size_t)N_NODES * 128];
__device__ __half g_supn[(size_t)N_NODES * 128];
__device__ float  g_self[(size_t)N_NODES * 128];
__device__ __nv_bfloat16 g_wt[9 * 128 * LDAB];   // 9 prepacked weight tiles

// ======================= CSR build =======================
__global__ void k_zero_rowptr() {
    int i = blockIdx.x * blockDim.x + threadIdx.x;
    if (i < NP1) g_rowptr[i] = 0;
}
__global__ void k_hist(const int* __restrict__ rows) {
    int e = blockIdx.x * blockDim.x + threadIdx.x;
    if (e < N_EDGES) atomicAdd(&g_rowptr[rows[e] + 1], 1);
}
__global__ void k_scan1() {
    __shared__ int s[1024];
    int t = threadIdx.x, i = blockIdx.x * 1024 + t;
    int v = (i < NP1) ? g_rowptr[i] : 0;
    s[t] = v; __syncthreads();
    #pragma unroll
    for (int off = 1; off < 1024; off <<= 1) {
        int tv = 0;
        if (t >= off) tv = s[t - off];
        __syncthreads(); s[t] += tv; __syncthreads();
    }
    if (i < NP1) g_rowptr[i] = s[t];
    if (t == 1023) g_bsum[blockIdx.x] = s[1023];
}
__global__ void k_scan2() {
    int acc = 0;
    for (int b = 0; b < NSCAN_BLOCKS; b++) { acc += g_bsum[b]; g_bsum[b] = acc; }
}
__global__ void k_scan3() {
    int b = blockIdx.x;
    if (b == 0) return;
    int i = b * 1024 + threadIdx.x;
    if (i < NP1) g_rowptr[i] += g_bsum[b - 1];
}
__global__ void k_copy_pos() {
    int i = blockIdx.x * blockDim.x + threadIdx.x;
    if (i < N_NODES) g_pos[i] = g_rowptr[i];
}
__global__ void k_fill(const int* __restrict__ rows, const int* __restrict__ cols,
                       const float* __restrict__ vals) {
    int e = blockIdx.x * blockDim.x + threadIdx.x;
    if (e >= N_EDGES) return;
    int r = rows[e];
    int p = atomicAdd(&g_pos[r], 1);
    g_ecol[p] = cols[e];
    g_eval[p] = vals[e];
}

// ======================= weight prep =======================
// Produce B tile [n=128][LDAB] bf16: hi at cols [0,128), lo at [128,256).
// mode 0: src0 (out,in): B[n][k] = s0[n*128+k]
// mode 1: src0 (in,out): B[n][k] = s0[k*128+n]
// mode 2: fused 64|64 (in,64): n<64 ? s0[k*64+n] : s1[k*64+n-64]
__global__ void k_wprep(const float* __restrict__ s0, const float* __restrict__ s1,
                        int mode, __nv_bfloat16* __restrict__ dst)
{
    int n = blockIdx.x, k = threadIdx.x;
    float v;
    if (mode == 0)      v = s0[n * 128 + k];
    else if (mode == 1) v = s0[k * 128 + n];
    else                v = (n < 64) ? s0[k * 64 + n] : s1[k * 64 + (n - 64)];
    __nv_bfloat16 hi = __float2bfloat16_rn(v);
    __nv_bfloat16 lo = __float2bfloat16_rn(v - __bfloat162float(hi));
    dst[n * LDAB + k]       = hi;
    dst[n * LDAB + 128 + k] = lo;
    if (k < 8) dst[n * LDAB + 256 + k] = __float2bfloat16_rn(0.f);
}

// ======================= wmma bf16 GEMM (3-term hi/lo split) =======================
// D[128,128] = X_tile[128,128] @ W^T; epilogue optional bias+relu, split dual output,
// optional fp16 conversion for output A.
#define MM_SMEM (2 * 128 * LDAB * 2 + 512)

__global__ __launch_bounds__(256, 1) void k_mm(
    const float* __restrict__ X,
    const __nv_bfloat16* __restrict__ Bw,
    const float* __restrict__ bias,
    void* __restrict__ outA, int ldA, int aHalf,
    float* __restrict__ outB, int ldB, int split)
{
    extern __shared__ char smraw[];
    __nv_bfloat16* As = (__nv_bfloat16*)smraw;                    // 128 x LDAB
    __nv_bfloat16* Bs = As + 128 * LDAB;                          // 128 x LDAB
    float* Cs    = (float*)smraw;                                 // overlays As (same bytes/row)
    float* biass = (float*)(smraw + 2 * 128 * LDAB * 2);

    const int tid = threadIdx.x, wid = tid >> 5, lane = tid & 31;
    const int row0 = blockIdx.x * 128;
    const bool hb = (bias != nullptr);

    if (hb && tid < 128) biass[tid] = bias[tid];

    // ---- load A tile, split fp32 -> bf16 hi/lo ----
    #pragma unroll
    for (int it = 0; it < 16; it++) {
        int idx = tid + 256 * it;          // 4096 float4 chunks
        int r = idx >> 5, c4 = idx & 31;
        float4 v = make_float4(0.f, 0.f, 0.f, 0.f);
        int row = row0 + r;
        if (row < N_NODES) v = *(const float4*)&X[(size_t)row * 128 + c4 * 4];
        __nv_bfloat16 hx = __float2bfloat16_rn(v.x);
        __nv_bfloat16 hy = __float2bfloat16_rn(v.y);
        __nv_bfloat16 hz = __float2bfloat16_rn(v.z);
        __nv_bfloat16 hw = __float2bfloat16_rn(v.w);
        __nv_bfloat16 lx = __float2bfloat16_rn(v.x - __bfloat162float(hx));
        __nv_bfloat16 ly = __float2bfloat16_rn(v.y - __bfloat162float(hy));
        __nv_bfloat16 lz = __float2bfloat16_rn(v.z - __bfloat162float(hz));
        __nv_bfloat16 lw = __float2bfloat16_rn(v.w - __bfloat162float(hw));
        __nv_bfloat16* ap = As + r * LDAB + c4 * 4;
        *(__nv_bfloat162*)(ap + 0)   = __halves2bfloat162(hx, hy);
        *(__nv_bfloat162*)(ap + 2)   = __halves2bfloat162(hz, hw);
        *(__nv_bfloat162*)(ap + 128) = __halves2bfloat162(lx, ly);
        *(__nv_bfloat162*)(ap + 130) = __halves2bfloat162(lz, lw);
    }

    // ---- copy prepacked B tile (67584 B = 4224 uint4) ----
    {
        const uint4* src = (const uint4*)Bw;
        uint4* dst = (uint4*)Bs;
        #pragma unroll
        for (int it = 0; it < 17; it++) {
            int i = tid + 256 * it;
            if (i < 4224) dst[i] = src[i];
        }
    }
    __syncthreads();

    // ---- compute: warp (wm, wn) owns 64x32 ----
    const int wm = wid >> 2, wn = wid & 3;

    wmma::fragment<wmma::accumulator, 16, 16, 16, float> cf[4][2];
    #pragma unroll
    for (int i = 0; i < 4; i++)
        #pragma unroll
        for (int j = 0; j < 2; j++)
            wmma::fill_fragment(cf[i][j], 0.f);

    const int kaOf[3] = {0, 0, 128};
    const int kbOf[3] = {0, 128, 0};

    #pragma unroll
    for (int p = 0; p < 3; p++) {
        #pragma unroll
        for (int ks = 0; ks < 8; ks++) {
            int ac = kaOf[p] + ks * 16;
            int bc = kbOf[p] + ks * 16;
            wmma::fragment<wmma::matrix_a, 16, 16, 16, __nv_bfloat16, wmma::row_major> af[4];
            wmma::fragment<wmma::matrix_b, 16, 16, 16, __nv_bfloat16, wmma::col_major> bfr[2];
            #pragma unroll
            for (int i = 0; i < 4; i++)
                wmma::load_matrix_sync(af[i], As + (wm * 64 + i * 16) * LDAB + ac, LDAB);
            #pragma unroll
            for (int j = 0; j < 2; j++)
                wmma::load_matrix_sync(bfr[j], Bs + (wn * 32 + j * 16) * LDAB + bc, LDAB);
            #pragma unroll
            for (int i = 0; i < 4; i++)
                #pragma unroll
                for (int j = 0; j < 2; j++)
                    wmma::mma_sync(cf[i][j], af[i], bfr[j], cf[i][j]);
        }
    }
    __syncthreads();   // done reading As; safe to overwrite with Cs

    #pragma unroll
    for (int i = 0; i < 4; i++)
        #pragma unroll
        for (int j = 0; j < 2; j++)
            wmma::store_matrix_sync(Cs + (wm * 64 + i * 16) * LDC + wn * 32 + j * 16,
                                    cf[i][j], LDC, wmma::mem_row_major);
    __syncthreads();

    // ---- epilogue: bias/relu, split dual output, optional fp16 ----
    #pragma unroll
    for (int it = 0; it < 16; it++) {
        int r = wid * 16 + it;
        int row = row0 + r;
        if (row >= N_NODES) continue;
        #pragma unroll
        for (int kk = 0; kk < 4; kk++) {
            int c = lane + 32 * kk;
            float v = Cs[r * LDC + c];
            if (hb) v = fmaxf(v + biass[c], 0.f);
            if (c < split) {
                if (aHalf) ((__half*)outA)[(size_t)row * ldA + c] = __float2half(v);
                else       ((float*)outA)[(size_t)row * ldA + c] = v;
            } else {
                outB[(size_t)row * ldB + (c - split)] = v;
            }
        }
    }
}

// ======================= LayerNorm =======================
__global__ __launch_bounds__(256) void k_ln(const float* __restrict__ in,
                                            float* __restrict__ out,
                                            const float* __restrict__ g,
                                            const float* __restrict__ b)
{
    int row  = blockIdx.x * 8 + (threadIdx.x >> 5);
    int lane = threadIdx.x & 31;
    float4 v = *(const float4*)&in[(size_t)row * 128 + lane * 4];
    float s = v.x + v.y + v.z + v.w;
    #pragma unroll
    for (int o = 16; o; o >>= 1) s += __shfl_xor_sync(0xffffffffu, s, o);
    float mean = s * (1.f / 128.f);
    float dx = v.x - mean, dy = v.y - mean, dz = v.z - mean, dw = v.w - mean;
    float ss = dx*dx + dy*dy + dz*dz + dw*dw;
    #pragma unroll
    for (int o = 16; o; o >>= 1) ss += __shfl_xor_sync(0xffffffffu, ss, o);
    float inv = 1.f / (sqrtf(ss * (1.f / 127.f)) + 1e-6f);
    float4 gg = *(const float4*)&g[lane * 4];
    float4 bb = *(const float4*)&b[lane * 4];
    float4 o4;
    o4.x = gg.x * dx * inv + bb.x;
    o4.y = gg.y * dy * inv + bb.y;
    o4.z = gg.z * dz * inv + bb.z;
    o4.w = gg.w * dw * inv + bb.w;
    *(float4*)&out[(size_t)row * 128 + lane * 4] = o4;
}

// ======================= GCN aggregate (fp16 gather) =======================
template <int OUT>
__global__ __launch_bounds__(256) void k_agg(const __half* __restrict__ supn,
                                             const float* __restrict__ selfm,
                                             const float* __restrict__ bias,
                                             float* __restrict__ out)
{
    const int V = OUT / 32;   // 4 or 2 floats per lane
    int node = blockIdx.x * 8 + (threadIdx.x >> 5);
    int lane = threadIdx.x & 31;

    float acc[V];
    {
        const float* sr = selfm + (size_t)node * OUT + lane * V;
        #pragma unroll
        for (int i = 0; i < V; i++) acc[i] = sr[i] + bias[lane * V + i];
    }

    int e0 = g_rowptr[node], e1 = g_rowptr[node + 1];
    for (int eb = e0; eb < e1; eb += 32) {
        int rem = e1 - eb;
        int c = 0; float wv = 0.f;
        if (lane < rem) { c = g_ecol[eb + lane]; wv = g_eval[eb + lane]; }
        if (rem >= 32) {
            #pragma unroll 8
            for (int j = 0; j < 32; j++) {
                int   cj = __shfl_sync(0xffffffffu, c, j);
                float wj = __shfl_sync(0xffffffffu, wv, j);
                const __half* srow = supn + (size_t)cj * OUT + lane * V;
                if (V == 4) {
                    uint2 u = *(const uint2*)srow;
                    float2 f0 = __half22float2(*(const __half2*)&u.x);
                    float2 f1 = __half22float2(*(const __half2*)&u.y);
                    acc[0] = fmaf(wj, f0.x, acc[0]);
                    acc[1] = fmaf(wj, f0.y, acc[1]);
                    acc[2] = fmaf(wj, f1.x, acc[2]);
                    acc[3] = fmaf(wj, f1.y, acc[3]);
                } else {
                    uint32_t u = *(const uint32_t*)srow;
                    float2 f0 = __half22float2(*(const __half2*)&u);
                    acc[0] = fmaf(wj, f0.x, acc[0]);
                    acc[1] = fmaf(wj, f0.y, acc[1]);
                }
            }
        } else {
            for (int j = 0; j < rem; j++) {
                int   cj = __shfl_sync(0xffffffffu, c, j);
                float wj = __shfl_sync(0xffffffffu, wv, j);
                const __half* srow = supn + (size_t)cj * OUT + lane * V;
                if (V == 4) {
                    uint2 u = *(const uint2*)srow;
                    float2 f0 = __half22float2(*(const __half2*)&u.x);
                    float2 f1 = __half22float2(*(const __half2*)&u.y);
                    acc[0] = fmaf(wj, f0.x, acc[0]);
                    acc[1] = fmaf(wj, f0.y, acc[1]);
                    acc[2] = fmaf(wj, f1.x, acc[2]);
                    acc[3] = fmaf(wj, f1.y, acc[3]);
                } else {
                    uint32_t u = *(const uint32_t*)srow;
                    float2 f0 = __half22float2(*(const __half2*)&u);
                    acc[0] = fmaf(wj, f0.x, acc[0]);
                    acc[1] = fmaf(wj, f0.y, acc[1]);
                }
            }
        }
    }

    float* orow = out + (size_t)node * OUT + lane * V;
    #pragma unroll
    for (int i = 0; i < V; i++) orow[i] = fmaxf(acc[i], 0.f);
}

// ======================= launch =======================
extern "C" void kernel_launch(void* const* d_in, const int* in_sizes, int n_in,
                              void* d_out, int out_size)
{
    const float* x    = (const float*)d_in[0];
    const int*   er   = (const int*)d_in[1];
    const int*   ec   = (const int*)d_in[2];
    const float* ev   = (const float*)d_in[3];
    const float* fc1w = (const float*)d_in[4];
    const float* fc1b = (const float*)d_in[5];
    const float* fc2w = (const float*)d_in[6];
    const float* fc2b = (const float*)d_in[7];
    const float* lng  = (const float*)d_in[8];
    const float* lnb  = (const float*)d_in[9];
    const float *wn[4], *wsf[4], *gb[4];
    for (int i = 0; i < 4; i++) {
        wn[i]  = (const float*)d_in[10 + 3 * i];
        wsf[i] = (const float*)d_in[11 + 3 * i];
        gb[i]  = (const float*)d_in[12 + 3 * i];
    }
    float* outp = (float*)d_out;

    float *h0, *h1, *selfb;
    __half* supn;
    __nv_bfloat16* wt;
    cudaGetSymbolAddress((void**)&h0,    g_h0);
    cudaGetSymbolAddress((void**)&h1,    g_h1);
    cudaGetSymbolAddress((void**)&supn,  g_supn);
    cudaGetSymbolAddress((void**)&selfb, g_self);
    cudaGetSymbolAddress((void**)&wt,    g_wt);
    auto WT = [&](int t) { return wt + (size_t)t * 128 * LDAB; };

    cudaFuncSetAttribute(k_mm, cudaFuncAttributeMaxDynamicSharedMemorySize, MM_SMEM);

    // ---- weight prep (9 tiles) ----
    k_wprep<<<128, 128>>>(fc1w, nullptr, 0, WT(0));
    k_wprep<<<128, 128>>>(fc2w, nullptr, 0, WT(1));
    for (int l = 0; l < 3; l++) {
        k_wprep<<<128, 128>>>(wn[l],  nullptr, 1, WT(2 + 2 * l));
        k_wprep<<<128, 128>>>(wsf[l], nullptr, 1, WT(3 + 2 * l));
    }
    k_wprep<<<128, 128>>>(wn[3], wsf[3], 2, WT(8));

    // ---- CSR build ----
    k_zero_rowptr<<<(NP1 + 255) / 256, 256>>>();
    k_hist<<<(N_EDGES + 255) / 256, 256>>>(er);
    k_scan1<<<NSCAN_BLOCKS, 1024>>>();
    k_scan2<<<1, 1>>>();
    k_scan3<<<NSCAN_BLOCKS, 1024>>>();
    k_copy_pos<<<(N_NODES + 255) / 256, 256>>>();
    k_fill<<<(N_EDGES + 255) / 256, 256>>>(er, ec, ev);

    const int MT = (N_NODES + 127) / 128;   // 782

    // ---- fc1, fc2, LN ----
    k_mm<<<MT, 256, MM_SMEM>>>(x,  WT(0), fc1b, h0, 128, 0, h0, 128, 128);
    k_mm<<<MT, 256, MM_SMEM>>>(h0, WT(1), fc2b, h1, 128, 0, h1, 128, 128);
    k_ln<<<N_NODES / 8, 256>>>(h1, h0, lng, lnb);

    // ---- GCN layers 1..3 (support -> fp16, self -> fp32) ----
    float* cur = h0;
    float* nxt = h1;
    for (int l = 0; l < 3; l++) {
        k_mm<<<MT, 256, MM_SMEM>>>(cur, WT(2 + 2 * l), nullptr, supn, 128, 1, nullptr, 128, 128);
        k_mm<<<MT, 256, MM_SMEM>>>(cur, WT(3 + 2 * l), nullptr, selfb, 128, 0, nullptr, 128, 128);
        k_agg<128><<<N_NODES / 8, 256>>>(supn, selfb, gb[l], nxt);
        float* t = cur; cur = nxt; nxt = t;
    }

    // ---- GCN layer 4: fused [wn|ws], cols<64 -> supn fp16, cols>=64 -> selfb fp32 ----
    k_mm<<<MT, 256, MM_SMEM>>>(cur, WT(8), nullptr, supn, 64, 1, selfb, 64, 64);
    k_agg<64><<<N_NODES / 8, 256>>>(supn, selfb, gb[3], outp);
}

// round 4
// speedup vs baseline: 1.4948x; 1.4336x over previous
#include <cuda_runtime.h>
#include <cuda_bf16.h>
#include <cuda_fp16.h>
#include <mma.h>
#include <math.h>
#include <stdint.h>

using namespace nvcuda;

#define N_NODES 100000
#define NPAD    100096
#define N_EDGES 3200000
#define NP1     100001
#define NSCAN_BLOCKS 98

#define LDAB 264   // bf16 elems per smem row: [hi 0..127 | lo 128..255 | pad]
#define LDC  132   // f32 elems per row (same 528 bytes)
#define A_BYTES (128 * LDAB * 2)          // 67584
#define BHALF_BYTES (128 * LDAB * 2)      // 67584 per 128 B-rows

// ======================= device scratch =======================
__device__ int    g_rowptr[NP1];
__device__ int    g_bsum[128];
__device__ int    g_pos[N_NODES];
__device__ int    g_ecol[N_EDGES];
__device__ float  g_eval[N_EDGES];
__device__ float  g_h0[(size_t)NPAD * 128];
__device__ float  g_h1[(size_t)NPAD * 128];
__device__ __half g_supn[(size_t)NPAD * 128];
__device__ float  g_self[(size_t)NPAD * 128];
__device__ __nv_bfloat16 g_wt[9 * 128 * LDAB];

// ======================= CSR build =======================
__global__ void k_zero_rowptr() {
    int i = blockIdx.x * blockDim.x + threadIdx.x;
    if (i < NP1) g_rowptr[i] = 0;
}
__global__ void k_hist(const int* __restrict__ rows) {
    int e = blockIdx.x * blockDim.x + threadIdx.x;
    if (e < N_EDGES) atomicAdd(&g_rowptr[rows[e] + 1], 1);
}
__global__ void k_scan1() {
    __shared__ int s[1024];
    int t = threadIdx.x, i = blockIdx.x * 1024 + t;
    int v = (i < NP1) ? g_rowptr[i] : 0;
    s[t] = v; __syncthreads();
    #pragma unroll
    for (int off = 1; off < 1024; off <<= 1) {
        int tv = 0;
        if (t >= off) tv = s[t - off];
        __syncthreads(); s[t] += tv; __syncthreads();
    }
    if (i < NP1) g_rowptr[i] = s[t];
    if (t == 1023) g_bsum[blockIdx.x] = s[1023];
}
__global__ void k_scan2() {
    int acc = 0;
    for (int b = 0; b < NSCAN_BLOCKS; b++) { acc += g_bsum[b]; g_bsum[b] = acc; }
}
__global__ void k_scan3() {
    int b = blockIdx.x;
    if (b == 0) return;
    int i = b * 1024 + threadIdx.x;
    if (i < NP1) g_rowptr[i] += g_bsum[b - 1];
}
__global__ void k_copy_pos() {
    int i = blockIdx.x * blockDim.x + threadIdx.x;
    if (i < N_NODES) g_pos[i] = g_rowptr[i];
}
__global__ void k_fill(const int* __restrict__ rows, const int* __restrict__ cols,
                       const float* __restrict__ vals) {
    int e = blockIdx.x * blockDim.x + threadIdx.x;
    if (e >= N_EDGES) return;
    int r = rows[e];
    int p = atomicAdd(&g_pos[r], 1);
    g_ecol[p] = cols[e];
    g_eval[p] = vals[e];
}

// ======================= weight prep (single launch, 9 tiles) =======================
// tiles 0,1: fc (out,in) -> B[n][k] = s[n*128+k]
// tiles 2..7: gc wn/ws (in,128) -> B[n][k] = s[k*128+n]
// tile 8: fused gc4 (in,64)|(in,64)
__global__ void k_wprep(const float* __restrict__ fc1w, const float* __restrict__ fc2w,
                        const float* __restrict__ w0n, const float* __restrict__ w0s,
                        const float* __restrict__ w1n, const float* __restrict__ w1s,
                        const float* __restrict__ w2n, const float* __restrict__ w2s,
                        const float* __restrict__ w3n, const float* __restrict__ w3s,
                        __nv_bfloat16* __restrict__ wt)
{
    int t = blockIdx.y, n = blockIdx.x, k = threadIdx.x;
    float v;
    switch (t) {
        case 0: v = fc1w[n * 128 + k]; break;
        case 1: v = fc2w[n * 128 + k]; break;
        case 2: v = w0n[k * 128 + n]; break;
        case 3: v = w0s[k * 128 + n]; break;
        case 4: v = w1n[k * 128 + n]; break;
        case 5: v = w1s[k * 128 + n]; break;
        case 6: v = w2n[k * 128 + n]; break;
        case 7: v = w2s[k * 128 + n]; break;
        default: v = (n < 64) ? w3n[k * 64 + n] : w3s[k * 64 + (n - 64)]; break;
    }
    __nv_bfloat16* dst = wt + (size_t)t * 128 * LDAB;
    __nv_bfloat16 hi = __float2bfloat16_rn(v);
    __nv_bfloat16 lo = __float2bfloat16_rn(v - __bfloat162float(hi));
    dst[n * LDAB + k]       = hi;
    dst[n * LDAB + 128 + k] = lo;
    if (k < 8) dst[n * LDAB + 256 + k] = __float2bfloat16_rn(0.f);
}

// ======================= wmma bf16 GEMM (3-term hi/lo) =======================
// D[128, nH*128] = X[128,128] @ W^T. Per half: (out, ld, mode)
//   mode 0: f32, bias+relu, smem path
//   mode 1: fp16, no bias, smem path
//   mode 2: f32, no bias, DIRECT fragment store (padded buffer required)
//   mode 3: split64: cols<64 -> fp16 oA(ld 64), cols>=64 -> f32 oB(ld 64)
__global__ __launch_bounds__(256, 1) void k_mm(
    const float* __restrict__ X,
    const __nv_bfloat16* __restrict__ Bw,
    const float* __restrict__ bias,
    void* __restrict__ o0, int ld0, int m0,
    void* __restrict__ o1, int ld1, int m1,
    int nH)
{
    extern __shared__ char smraw[];
    __nv_bfloat16* As = (__nv_bfloat16*)smraw;             // 128 x LDAB
    __nv_bfloat16* Bs = As + 128 * LDAB;                   // nH*128 x LDAB
    float* biass = (float*)(smraw + A_BYTES + nH * BHALF_BYTES);

    const int tid = threadIdx.x, wid = tid >> 5, lane = tid & 31;
    const int row0 = blockIdx.x * 128;
    const bool hb = (bias != nullptr);

    if (hb && tid < 128) biass[tid] = bias[tid];

    // ---- load A tile, split fp32 -> bf16 hi/lo ----
    #pragma unroll
    for (int it = 0; it < 16; it++) {
        int idx = tid + 256 * it;
        int r = idx >> 5, c4 = idx & 31;
        float4 v = make_float4(0.f, 0.f, 0.f, 0.f);
        int row = row0 + r;
        if (row < N_NODES) v = *(const float4*)&X[(size_t)row * 128 + c4 * 4];
        __nv_bfloat16 hx = __float2bfloat16_rn(v.x);
        __nv_bfloat16 hy = __float2bfloat16_rn(v.y);
        __nv_bfloat16 hz = __float2bfloat16_rn(v.z);
        __nv_bfloat16 hw = __float2bfloat16_rn(v.w);
        __nv_bfloat16 lx = __float2bfloat16_rn(v.x - __bfloat162float(hx));
        __nv_bfloat16 ly = __float2bfloat16_rn(v.y - __bfloat162float(hy));
        __nv_bfloat16 lz = __float2bfloat16_rn(v.z - __bfloat162float(hz));
        __nv_bfloat16 lw = __float2bfloat16_rn(v.w - __bfloat162float(hw));
        __nv_bfloat16* ap = As + r * LDAB + c4 * 4;
        *(__nv_bfloat162*)(ap + 0)   = __halves2bfloat162(hx, hy);
        *(__nv_bfloat162*)(ap + 2)   = __halves2bfloat162(hz, hw);
        *(__nv_bfloat162*)(ap + 128) = __halves2bfloat162(lx, ly);
        *(__nv_bfloat162*)(ap + 130) = __halves2bfloat162(lz, lw);
    }

    // ---- copy prepacked B (nH * 4224 uint4) ----
    {
        const uint4* src = (const uint4*)Bw;
        uint4* dst = (uint4*)Bs;
        int tot = nH * 4224;
        for (int i = tid; i < tot; i += 256) dst[i] = src[i];
    }
    __syncthreads();

    const int wm = wid >> 2, wn = wid & 3;
    const int kaOf[3] = {0, 0, 128};
    const int kbOf[3] = {0, 128, 0};

    for (int nh = 0; nh < nH; nh++) {
        const __nv_bfloat16* Bh = Bs + nh * 128 * LDAB;
        void* oh = (nh == 0) ? o0 : o1;
        int   ldh = (nh == 0) ? ld0 : ld1;
        int   mh = (nh == 0) ? m0 : m1;

        wmma::fragment<wmma::accumulator, 16, 16, 16, float> cf[4][2];
        #pragma unroll
        for (int i = 0; i < 4; i++)
            #pragma unroll
            for (int j = 0; j < 2; j++)
                wmma::fill_fragment(cf[i][j], 0.f);

        #pragma unroll
        for (int p = 0; p < 3; p++) {
            #pragma unroll
            for (int ks = 0; ks < 8; ks++) {
                int ac = kaOf[p] + ks * 16;
                int bc = kbOf[p] + ks * 16;
                wmma::fragment<wmma::matrix_a, 16, 16, 16, __nv_bfloat16, wmma::row_major> af[4];
                wmma::fragment<wmma::matrix_b, 16, 16, 16, __nv_bfloat16, wmma::col_major> bfr[2];
                #pragma unroll
                for (int i = 0; i < 4; i++)
                    wmma::load_matrix_sync(af[i], As + (wm * 64 + i * 16) * LDAB + ac, LDAB);
                #pragma unroll
                for (int j = 0; j < 2; j++)
                    wmma::load_matrix_sync(bfr[j], Bh + (wn * 32 + j * 16) * LDAB + bc, LDAB);
                #pragma unroll
                for (int i = 0; i < 4; i++)
                    #pragma unroll
                    for (int j = 0; j < 2; j++)
                        wmma::mma_sync(cf[i][j], af[i], bfr[j], cf[i][j]);
            }
        }

        if (mh == 2) {
            // direct fragment store to (padded) fp32 buffer, no sync needed
            float* ob = (float*)oh;
            #pragma unroll
            for (int i = 0; i < 4; i++)
                #pragma unroll
                for (int j = 0; j < 2; j++)
                    wmma::store_matrix_sync(
                        ob + (size_t)(row0 + wm * 64 + i * 16) * ldh + wn * 32 + j * 16,
                        cf[i][j], ldh, wmma::mem_row_major);
        } else {
            __syncthreads();   // all warps done reading B half nh -> overlay Cs on it
            float* Cs = (float*)Bh;
            #pragma unroll
            for (int i = 0; i < 4; i++)
                #pragma unroll
                for (int j = 0; j < 2; j++)
                    wmma::store_matrix_sync(Cs + (wm * 64 + i * 16) * LDC + wn * 32 + j * 16,
                                            cf[i][j], LDC, wmma::mem_row_major);
            __syncthreads();

            #pragma unroll
            for (int it = 0; it < 16; it++) {
                int r = wid * 16 + it;
                int row = row0 + r;
                if (row >= N_NODES) continue;
                #pragma unroll
                for (int kk = 0; kk < 4; kk++) {
                    int c = lane + 32 * kk;
                    float v = Cs[r * LDC + c];
                    if (mh == 0) {
                        v = fmaxf(v + biass[c], 0.f);
                        ((float*)oh)[(size_t)row * ldh + c] = v;
                    } else if (mh == 1) {
                        ((__half*)oh)[(size_t)row * ldh + c] = __float2half(v);
                    } else {   // mode 3: split 64/64
                        if (c < 64)
                            ((__half*)oh)[(size_t)row * 64 + c] = __float2half(v);
                        else
                            ((float*)o1)[(size_t)row * 64 + (c - 64)] = v;
                    }
                }
            }
            __syncthreads();   // Cs reads done before any later overlay reuse
        }
    }
}

// ======================= LayerNorm =======================
__global__ __launch_bounds__(256) void k_ln(const float* __restrict__ in,
                                            float* __restrict__ out,
                                            const float* __restrict__ g,
                                            const float* __restrict__ b)
{
    int row  = blockIdx.x * 8 + (threadIdx.x >> 5);
    int lane = threadIdx.x & 31;
    float4 v = *(const float4*)&in[(size_t)row * 128 + lane * 4];
    float s = v.x + v.y + v.z + v.w;
    #pragma unroll
    for (int o = 16; o; o >>= 1) s += __shfl_xor_sync(0xffffffffu, s, o);
    float mean = s * (1.f / 128.f);
    float dx = v.x - mean, dy = v.y - mean, dz = v.z - mean, dw = v.w - mean;
    float ss = dx*dx + dy*dy + dz*dz + dw*dw;
    #pragma unroll
    for (int o = 16; o; o >>= 1) ss += __shfl_xor_sync(0xffffffffu, ss, o);
    float inv = 1.f / (sqrtf(ss * (1.f / 127.f)) + 1e-6f);
    float4 gg = *(const float4*)&g[lane * 4];
    float4 bb = *(const float4*)&b[lane * 4];
    float4 o4;
    o4.x = gg.x * dx * inv + bb.x;
    o4.y = gg.y * dy * inv + bb.y;
    o4.z = gg.z * dz * inv + bb.z;
    o4.w = gg.w * dw * inv + bb.w;
    *(float4*)&out[(size_t)row * 128 + lane * 4] = o4;
}

// ======================= GCN aggregate (fp16 gather) =======================
template <int OUT>
__global__ __launch_bounds__(256) void k_agg(const __half* __restrict__ supn,
                                             const float* __restrict__ selfm,
                                             const float* __restrict__ bias,
                                             float* __restrict__ out)
{
    const int V = OUT / 32;
    int node = blockIdx.x * 8 + (threadIdx.x >> 5);
    int lane = threadIdx.x & 31;

    float acc[V];
    {
        const float* sr = selfm + (size_t)node * OUT + lane * V;
        #pragma unroll
        for (int i = 0; i < V; i++) acc[i] = sr[i] + bias[lane * V + i];
    }

    int e0 = g_rowptr[node], e1 = g_rowptr[node + 1];
    for (int eb = e0; eb < e1; eb += 32) {
        int rem = e1 - eb;
        int c = 0; float wv = 0.f;
        if (lane < rem) { c = g_ecol[eb + lane]; wv = g_eval[eb + lane]; }
        if (rem >= 32) {
            #pragma unroll 8
            for (int j = 0; j < 32; j++) {
                int   cj = __shfl_sync(0xffffffffu, c, j);
                float wj = __shfl_sync(0xffffffffu, wv, j);
                const __half* srow = supn + (size_t)cj * OUT + lane * V;
                if (V == 4) {
                    uint2 u = *(const uint2*)srow;
                    float2 f0 = __half22float2(*(const __half2*)&u.x);
                    float2 f1 = __half22float2(*(const __half2*)&u.y);
                    acc[0] = fmaf(wj, f0.x, acc[0]);
                    acc[1] = fmaf(wj, f0.y, acc[1]);
                    acc[2] = fmaf(wj, f1.x, acc[2]);
                    acc[3] = fmaf(wj, f1.y, acc[3]);
                } else {
                    uint32_t u = *(const uint32_t*)srow;
                    float2 f0 = __half22float2(*(const __half2*)&u);
                    acc[0] = fmaf(wj, f0.x, acc[0]);
                    acc[1] = fmaf(wj, f0.y, acc[1]);
                }
            }
        } else {
            for (int j = 0; j < rem; j++) {
                int   cj = __shfl_sync(0xffffffffu, c, j);
                float wj = __shfl_sync(0xffffffffu, wv, j);
                const __half* srow = supn + (size_t)cj * OUT + lane * V;
                if (V == 4) {
                    uint2 u = *(const uint2*)srow;
                    float2 f0 = __half22float2(*(const __half2*)&u.x);
                    float2 f1 = __half22float2(*(const __half2*)&u.y);
                    acc[0] = fmaf(wj, f0.x, acc[0]);
                    acc[1] = fmaf(wj, f0.y, acc[1]);
                    acc[2] = fmaf(wj, f1.x, acc[2]);
                    acc[3] = fmaf(wj, f1.y, acc[3]);
                } else {
                    uint32_t u = *(const uint32_t*)srow;
                    float2 f0 = __half22float2(*(const __half2*)&u);
                    acc[0] = fmaf(wj, f0.x, acc[0]);
                    acc[1] = fmaf(wj, f0.y, acc[1]);
                }
            }
        }
    }

    float* orow = out + (size_t)node * OUT + lane * V;
    #pragma unroll
    for (int i = 0; i < V; i++) orow[i] = fmaxf(acc[i], 0.f);
}

// ======================= launch =======================
extern "C" void kernel_launch(void* const* d_in, const int* in_sizes, int n_in,
                              void* d_out, int out_size)
{
    const float* x    = (const float*)d_in[0];
    const int*   er   = (const int*)d_in[1];
    const int*   ec   = (const int*)d_in[2];
    const float* ev   = (const float*)d_in[3];
    const float* fc1w = (const float*)d_in[4];
    const float* fc1b = (const float*)d_in[5];
    const float* fc2w = (const float*)d_in[6];
    const float* fc2b = (const float*)d_in[7];
    const float* lng  = (const float*)d_in[8];
    const float* lnb  = (const float*)d_in[9];
    const float *wn[4], *wsf[4], *gb[4];
    for (int i = 0; i < 4; i++) {
        wn[i]  = (const float*)d_in[10 + 3 * i];
        wsf[i] = (const float*)d_in[11 + 3 * i];
        gb[i]  = (const float*)d_in[12 + 3 * i];
    }
    float* outp = (float*)d_out;

    float *h0, *h1, *selfb;
    __half* supn;
    __nv_bfloat16* wt;
    cudaGetSymbolAddress((void**)&h0,    g_h0);
    cudaGetSymbolAddress((void**)&h1,    g_h1);
    cudaGetSymbolAddress((void**)&supn,  g_supn);
    cudaGetSymbolAddress((void**)&selfb, g_self);
    cudaGetSymbolAddress((void**)&wt,    g_wt);
    auto WT = [&](int t) { return wt + (size_t)t * 128 * LDAB; };

    const int SM1 = A_BYTES + 1 * BHALF_BYTES + 1024;   // nH=1
    const int SM2 = A_BYTES + 2 * BHALF_BYTES + 1024;   // nH=2
    cudaFuncSetAttribute(k_mm, cudaFuncAttributeMaxDynamicSharedMemorySize, SM2);

    const int MT = (N_NODES + 127) / 128;   // 782

    // launch order arranged so index 5 (ncu -s 5 -c 1) = first k_mm
    k_wprep<<<dim3(128, 9), 128>>>(fc1w, fc2w, wn[0], wsf[0], wn[1], wsf[1],
                                   wn[2], wsf[2], wn[3], wsf[3], wt);          // 0
    k_zero_rowptr<<<(NP1 + 255) / 256, 256>>>();                                // 1
    k_hist<<<(N_EDGES + 255) / 256, 256>>>(er);                                 // 2
    k_scan1<<<NSCAN_BLOCKS, 1024>>>();                                          // 3
    k_scan2<<<1, 1>>>();                                                        // 4
    k_mm<<<MT, 256, SM1>>>(x, WT(0), fc1b, h0, 128, 0, nullptr, 0, 0, 1);       // 5  <- profiled
    k_scan3<<<NSCAN_BLOCKS, 1024>>>();                                          // 6
    k_copy_pos<<<(N_NODES + 255) / 256, 256>>>();                               // 7
    k_fill<<<(N_EDGES + 255) / 256, 256>>>(er, ec, ev);                         // 8
    k_mm<<<MT, 256, SM1>>>(h0, WT(1), fc2b, h1, 128, 0, nullptr, 0, 0, 1);      // 9
    k_ln<<<N_NODES / 8, 256>>>(h1, h0, lng, lnb);                               // 10

    float* cur = h0;
    float* nxt = h1;
    for (int l = 0; l < 3; l++) {
        k_mm<<<MT, 256, SM2>>>(cur, WT(2 + 2 * l), nullptr,
                               supn, 128, 1, selfb, 128, 2, 2);
        k_agg<128><<<N_NODES / 8, 256>>>(supn, selfb, gb[l], nxt);
        float* t = cur; cur = nxt; nxt = t;
    }

    k_mm<<<MT, 256, SM1>>>(cur, WT(8), nullptr, supn, 64, 3, selfb, 64, 0, 1);
    k_agg<64><<<N_NODES / 8, 256>>>(supn, selfb, gb[3], outp);
}

// round 5
// speedup vs baseline: 1.6688x; 1.1164x over previous
#include <cuda_runtime.h>
#include <cuda_bf16.h>
#include <cuda_fp16.h>
#include <math.h>
#include <stdint.h>

#define N_NODES 100000
#define NPAD    100096
#define N_EDGES 3200000
#define NP1     100001
#define NSCAN_BLOCKS 98

#define LDAB 264   // bf16 elems per row: [hi 0..127 | lo 128..255 | pad]
#define A_BYTES (128 * LDAB * 2)   // 67584

// ======================= device scratch =======================
__device__ int    g_rowptr[NP1];
__device__ int    g_bsum[128];
__device__ int    g_pos[N_NODES];
__device__ int    g_ecol[N_EDGES];
__device__ float  g_eval[N_EDGES];
__device__ float  g_h0[(size_t)NPAD * 128];
__device__ float  g_h1[(size_t)NPAD * 128];
__device__ __half g_supn[(size_t)NPAD * 128];
__device__ float  g_self[(size_t)NPAD * 128];
__device__ __nv_bfloat16 g_wt[9 * 128 * LDAB];

// ======================= helpers =======================
__device__ __forceinline__ uint32_t smem_u32(const void* p) {
    uint32_t a;
    asm("{ .reg .u64 t; cvta.to.shared.u64 t, %1; cvt.u32.u64 %0, t; }" : "=r"(a) : "l"(p));
    return a;
}
__device__ __forceinline__ void ldsm_x4(unsigned* r, uint32_t addr) {
    asm volatile("ldmatrix.sync.aligned.m8n8.x4.shared.b16 {%0,%1,%2,%3}, [%4];"
        : "=r"(r[0]), "=r"(r[1]), "=r"(r[2]), "=r"(r[3]) : "r"(addr));
}
__device__ __forceinline__ void mma_bf16(float* c, const unsigned* a, const unsigned* b) {
    asm volatile("mma.sync.aligned.m16n8k16.row.col.f32.bf16.bf16.f32 "
        "{%0,%1,%2,%3}, {%4,%5,%6,%7}, {%8,%9}, {%0,%1,%2,%3};"
        : "+f"(c[0]), "+f"(c[1]), "+f"(c[2]), "+f"(c[3])
        : "r"(a[0]), "r"(a[1]), "r"(a[2]), "r"(a[3]), "r"(b[0]), "r"(b[1]));
}

// ======================= CSR build =======================
__global__ void k_zero_rowptr() {
    int i = blockIdx.x * blockDim.x + threadIdx.x;
    if (i < NP1) g_rowptr[i] = 0;
}
__global__ void k_hist(const int* __restrict__ rows) {
    int e = blockIdx.x * blockDim.x + threadIdx.x;
    if (e < N_EDGES) atomicAdd(&g_rowptr[rows[e] + 1], 1);
}
__global__ void k_scan1() {
    __shared__ int s[1024];
    int t = threadIdx.x, i = blockIdx.x * 1024 + t;
    int v = (i < NP1) ? g_rowptr[i] : 0;
    s[t] = v; __syncthreads();
    #pragma unroll
    for (int off = 1; off < 1024; off <<= 1) {
        int tv = 0;
        if (t >= off) tv = s[t - off];
        __syncthreads(); s[t] += tv; __syncthreads();
    }
    if (i < NP1) g_rowptr[i] = s[t];
    if (t == 1023) g_bsum[blockIdx.x] = s[1023];
}
__global__ void k_scan2() {
    int acc = 0;
    for (int b = 0; b < NSCAN_BLOCKS; b++) { acc += g_bsum[b]; g_bsum[b] = acc; }
}
__global__ void k_scan3() {
    int b = blockIdx.x;
    if (b == 0) return;
    int i = b * 1024 + threadIdx.x;
    if (i < NP1) g_rowptr[i] += g_bsum[b - 1];
}
__global__ void k_copy_pos() {
    int i = blockIdx.x * blockDim.x + threadIdx.x;
    if (i < N_NODES) g_pos[i] = g_rowptr[i];
}
__global__ void k_fill(const int* __restrict__ rows, const int* __restrict__ cols,
                       const float* __restrict__ vals) {
    int e = blockIdx.x * blockDim.x + threadIdx.x;
    if (e >= N_EDGES) return;
    int r = rows[e];
    int p = atomicAdd(&g_pos[r], 1);
    g_ecol[p] = cols[e];
    g_eval[p] = vals[e];
}

// ======================= weight prep =======================
__global__ void k_wprep(const float* __restrict__ fc1w, const float* __restrict__ fc2w,
                        const float* __restrict__ w0n, const float* __restrict__ w0s,
                        const float* __restrict__ w1n, const float* __restrict__ w1s,
                        const float* __restrict__ w2n, const float* __restrict__ w2s,
                        const float* __restrict__ w3n, const float* __restrict__ w3s,
                        __nv_bfloat16* __restrict__ wt)
{
    int t = blockIdx.y, n = blockIdx.x, k = threadIdx.x;
    float v;
    switch (t) {
        case 0: v = fc1w[n * 128 + k]; break;
        case 1: v = fc2w[n * 128 + k]; break;
        case 2: v = w0n[k * 128 + n]; break;
        case 3: v = w0s[k * 128 + n]; break;
        case 4: v = w1n[k * 128 + n]; break;
        case 5: v = w1s[k * 128 + n]; break;
        case 6: v = w2n[k * 128 + n]; break;
        case 7: v = w2s[k * 128 + n]; break;
        default: v = (n < 64) ? w3n[k * 64 + n] : w3s[k * 64 + (n - 64)]; break;
    }
    __nv_bfloat16* dst = wt + (size_t)t * 128 * LDAB;
    __nv_bfloat16 hi = __float2bfloat16_rn(v);
    __nv_bfloat16 lo = __float2bfloat16_rn(v - __bfloat162float(hi));
    dst[n * LDAB + k]       = hi;
    dst[n * LDAB + 128 + k] = lo;
    if (k < 8) dst[n * LDAB + 256 + k] = __float2bfloat16_rn(0.f);
}

// ======================= mma.sync bf16 GEMM (3-term hi/lo) =======================
// D[128, nH*128] = X[128,128] @ W^T. smem: A tile only. B read from global (L2).
// modes: 0 = f32 bias+relu (ld128); 1 = fp16 (ld128); 2 = f32 raw (ld128);
//        3 = split64: wn<2 -> fp16 o0 (ld64), wn>=2 -> f32 o1 (ld64)
__global__ __launch_bounds__(256, 2) void k_mm(
    const float* __restrict__ X,
    const __nv_bfloat16* __restrict__ Bw,
    const float* __restrict__ bias,
    void* __restrict__ o0, int m0,
    void* __restrict__ o1, int m1,
    int nH)
{
    extern __shared__ __nv_bfloat16 As[];   // 128 x LDAB

    const int tid = threadIdx.x, wid = tid >> 5, lane = tid & 31;
    const int wm = wid >> 2, wn = wid & 3;     // warp tile: 64 rows x 32 cols
    const int row0 = blockIdx.x * 128;

    // ---- load A tile, split fp32 -> bf16 hi/lo ----
    #pragma unroll
    for (int it = 0; it < 16; it++) {
        int idx = tid + 256 * it;
        int r = idx >> 5, c4 = idx & 31;
        float4 v = make_float4(0.f, 0.f, 0.f, 0.f);
        int row = row0 + r;
        if (row < N_NODES) v = *(const float4*)&X[(size_t)row * 128 + c4 * 4];
        __nv_bfloat16 hx = __float2bfloat16_rn(v.x);
        __nv_bfloat16 hy = __float2bfloat16_rn(v.y);
        __nv_bfloat16 hz = __float2bfloat16_rn(v.z);
        __nv_bfloat16 hw = __float2bfloat16_rn(v.w);
        __nv_bfloat16 lx = __float2bfloat16_rn(v.x - __bfloat162float(hx));
        __nv_bfloat16 ly = __float2bfloat16_rn(v.y - __bfloat162float(hy));
        __nv_bfloat16 lz = __float2bfloat16_rn(v.z - __bfloat162float(hz));
        __nv_bfloat16 lw = __float2bfloat16_rn(v.w - __bfloat162float(hw));
        __nv_bfloat16* ap = As + r * LDAB + c4 * 4;
        *(__nv_bfloat162*)(ap + 0)   = __halves2bfloat162(hx, hy);
        *(__nv_bfloat162*)(ap + 2)   = __halves2bfloat162(hz, hw);
        *(__nv_bfloat162*)(ap + 128) = __halves2bfloat162(lx, ly);
        *(__nv_bfloat162*)(ap + 130) = __halves2bfloat162(lz, lw);
    }
    __syncthreads();

    // per-lane ldmatrix base: rows (lane&15), k-half (lane>>4)*8
    const uint32_t aBase = smem_u32(As) +
        2u * (uint32_t)((wm * 64 + (lane & 15)) * LDAB + ((lane >> 4) << 3));

    for (int nh = 0; nh < nH; nh++) {
        const __nv_bfloat16* Bh = Bw + (size_t)nh * 128 * LDAB;
        // per-lane B base: n = wn*32 + lane/4, k = 2*(lane%4)
        const __nv_bfloat16* bBase = Bh + (size_t)(wn * 32 + (lane >> 2)) * LDAB + 2 * (lane & 3);

        float acc[4][4][4];
        #pragma unroll
        for (int i = 0; i < 4; i++)
            #pragma unroll
            for (int j = 0; j < 4; j++)
                #pragma unroll
                for (int q = 0; q < 4; q++) acc[i][j][q] = 0.f;

        #pragma unroll
        for (int ks = 0; ks < 8; ks++) {
            const int ka = ks * 16;
            unsigned ah[4][4], bh[4][2];
            #pragma unroll
            for (int i = 0; i < 4; i++)
                ldsm_x4(ah[i], aBase + 2u * (uint32_t)(i * 16 * LDAB + ka));
            #pragma unroll
            for (int j = 0; j < 4; j++) {
                const __nv_bfloat16* p = bBase + j * 8 * LDAB + ka;
                bh[j][0] = *(const unsigned*)p;
                bh[j][1] = *(const unsigned*)(p + 8);
            }
            #pragma unroll
            for (int i = 0; i < 4; i++)
                #pragma unroll
                for (int j = 0; j < 4; j++)
                    mma_bf16(acc[i][j], ah[i], bh[j]);
            // A-lo x B-hi
            {
                unsigned al[4][4];
                #pragma unroll
                for (int i = 0; i < 4; i++)
                    ldsm_x4(al[i], aBase + 2u * (uint32_t)(i * 16 * LDAB + ka + 128));
                #pragma unroll
                for (int i = 0; i < 4; i++)
                    #pragma unroll
                    for (int j = 0; j < 4; j++)
                        mma_bf16(acc[i][j], al[i], bh[j]);
            }
            // A-hi x B-lo
            {
                unsigned bl[4][2];
                #pragma unroll
                for (int j = 0; j < 4; j++) {
                    const __nv_bfloat16* p = bBase + j * 8 * LDAB + ka + 128;
                    bl[j][0] = *(const unsigned*)p;
                    bl[j][1] = *(const unsigned*)(p + 8);
                }
                #pragma unroll
                for (int i = 0; i < 4; i++)
                    #pragma unroll
                    for (int j = 0; j < 4; j++)
                        mma_bf16(acc[i][j], ah[i], bl[j]);
            }
        }

        // ---- register epilogue (all outputs NPAD-padded: no row guard) ----
        const int mode = (nh == 0) ? m0 : m1;
        const int cb = wn * 32 + 2 * (lane & 3);
        const int rb = row0 + wm * 64 + (lane >> 2);

        if (mode == 0) {
            float2 bv[4];
            #pragma unroll
            for (int j = 0; j < 4; j++) bv[j] = *(const float2*)&bias[cb + j * 8];
            float* out = (float*)o0;
            #pragma unroll
            for (int i = 0; i < 4; i++) {
                size_t r1 = (size_t)(rb + i * 16) * 128;
                size_t r2 = r1 + 8 * 128;
                #pragma unroll
                for (int j = 0; j < 4; j++) {
                    float* a = acc[i][j];
                    int c = cb + j * 8;
                    *(float2*)&out[r1 + c] = make_float2(fmaxf(a[0] + bv[j].x, 0.f),
                                                         fmaxf(a[1] + bv[j].y, 0.f));
                    *(float2*)&out[r2 + c] = make_float2(fmaxf(a[2] + bv[j].x, 0.f),
                                                         fmaxf(a[3] + bv[j].y, 0.f));
                }
            }
        } else if (mode == 1) {
            __half* out = (__half*)o0;
            #pragma unroll
            for (int i = 0; i < 4; i++) {
                size_t r1 = (size_t)(rb + i * 16) * 128;
                size_t r2 = r1 + 8 * 128;
                #pragma unroll
                for (int j = 0; j < 4; j++) {
                    float* a = acc[i][j];
                    int c = cb + j * 8;
                    *(__half2*)&out[r1 + c] = __floats2half2_rn(a[0], a[1]);
                    *(__half2*)&out[r2 + c] = __floats2half2_rn(a[2], a[3]);
                }
            }
        } else if (mode == 2) {
            float* out = (float*)o1;
            #pragma unroll
            for (int i = 0; i < 4; i++) {
                size_t r1 = (size_t)(rb + i * 16) * 128;
                size_t r2 = r1 + 8 * 128;
                #pragma unroll
                for (int j = 0; j < 4; j++) {
                    float* a = acc[i][j];
                    int c = cb + j * 8;
                    *(float2*)&out[r1 + c] = make_float2(a[0], a[1]);
                    *(float2*)&out[r2 + c] = make_float2(a[2], a[3]);
                }
            }
        } else {   // mode 3: cols<64 -> fp16 o0 (ld 64); cols>=64 -> f32 o1 (ld 64)
            if (wn < 2) {
                __half* out = (__half*)o0;
                #pragma unroll
                for (int i = 0; i < 4; i++) {
                    size_t r1 = (size_t)(rb + i * 16) * 64;
                    size_t r2 = r1 + 8 * 64;
                    #pragma unroll
                    for (int j = 0; j < 4; j++) {
                        float* a = acc[i][j];
                        int c = cb + j * 8;
                        *(__half2*)&out[r1 + c] = __floats2half2_rn(a[0], a[1]);
                        *(__half2*)&out[r2 + c] = __floats2half2_rn(a[2], a[3]);
                    }
                }
            } else {
                float* out = (float*)o1;
                #pragma unroll
                for (int i = 0; i < 4; i++) {
                    size_t r1 = (size_t)(rb + i * 16) * 64;
                    size_t r2 = r1 + 8 * 64;
                    #pragma unroll
                    for (int j = 0; j < 4; j++) {
                        float* a = acc[i][j];
                        int c = cb + j * 8 - 64;
                        *(float2*)&out[r1 + c] = make_float2(a[0], a[1]);
                        *(float2*)&out[r2 + c] = make_float2(a[2], a[3]);
                    }
                }
            }
        }
    }
}

// ======================= LayerNorm =======================
__global__ __launch_bounds__(256) void k_ln(const float* __restrict__ in,
                                            float* __restrict__ out,
                                            const float* __restrict__ g,
                                            const float* __restrict__ b)
{
    int row  = blockIdx.x * 8 + (threadIdx.x >> 5);
    int lane = threadIdx.x & 31;
    float4 v = *(const float4*)&in[(size_t)row * 128 + lane * 4];
    float s = v.x + v.y + v.z + v.w;
    #pragma unroll
    for (int o = 16; o; o >>= 1) s += __shfl_xor_sync(0xffffffffu, s, o);
    float mean = s * (1.f / 128.f);
    float dx = v.x - mean, dy = v.y - mean, dz = v.z - mean, dw = v.w - mean;
    float ss = dx*dx + dy*dy + dz*dz + dw*dw;
    #pragma unroll
    for (int o = 16; o; o >>= 1) ss += __shfl_xor_sync(0xffffffffu, ss, o);
    float inv = 1.f / (sqrtf(ss * (1.f / 127.f)) + 1e-6f);
    float4 gg = *(const float4*)&g[lane * 4];
    float4 bb = *(const float4*)&b[lane * 4];
    float4 o4;
    o4.x = gg.x * dx * inv + bb.x;
    o4.y = gg.y * dy * inv + bb.y;
    o4.z = gg.z * dz * inv + bb.z;
    o4.w = gg.w * dw * inv + bb.w;
    *(float4*)&out[(size_t)row * 128 + lane * 4] = o4;
}

// ======================= GCN aggregate (fp16 gather) =======================
template <int OUT>
__global__ __launch_bounds__(256) void k_agg(const __half* __restrict__ supn,
                                             const float* __restrict__ selfm,
                                             const float* __restrict__ bias,
                                             float* __restrict__ out)
{
    const int V = OUT / 32;
    int node = blockIdx.x * 8 + (threadIdx.x >> 5);
    int lane = threadIdx.x & 31;

    float acc[V];
    {
        const float* sr = selfm + (size_t)node * OUT + lane * V;
        #pragma unroll
        for (int i = 0; i < V; i++) acc[i] = sr[i] + bias[lane * V + i];
    }

    int e0 = g_rowptr[node], e1 = g_rowptr[node + 1];
    for (int eb = e0; eb < e1; eb += 32) {
        int rem = e1 - eb;
        int c = 0; float wv = 0.f;
        if (lane < rem) { c = g_ecol[eb + lane]; wv = g_eval[eb + lane]; }
        if (rem >= 32) {
            #pragma unroll 8
            for (int j = 0; j < 32; j++) {
                int   cj = __shfl_sync(0xffffffffu, c, j);
                float wj = __shfl_sync(0xffffffffu, wv, j);
                const __half* srow = supn + (size_t)cj * OUT + lane * V;
                if (V == 4) {
                    uint2 u = *(const uint2*)srow;
                    float2 f0 = __half22float2(*(const __half2*)&u.x);
                    float2 f1 = __half22float2(*(const __half2*)&u.y);
                    acc[0] = fmaf(wj, f0.x, acc[0]);
                    acc[1] = fmaf(wj, f0.y, acc[1]);
                    acc[2] = fmaf(wj, f1.x, acc[2]);
                    acc[3] = fmaf(wj, f1.y, acc[3]);
                } else {
                    uint32_t u = *(const uint32_t*)srow;
                    float2 f0 = __half22float2(*(const __half2*)&u);
                    acc[0] = fmaf(wj, f0.x, acc[0]);
                    acc[1] = fmaf(wj, f0.y, acc[1]);
                }
            }
        } else {
            for (int j = 0; j < rem; j++) {
                int   cj = __shfl_sync(0xffffffffu, c, j);
                float wj = __shfl_sync(0xffffffffu, wv, j);
                const __half* srow = supn + (size_t)cj * OUT + lane * V;
                if (V == 4) {
                    uint2 u = *(const uint2*)srow;
                    float2 f0 = __half22float2(*(const __half2*)&u.x);
                    float2 f1 = __half22float2(*(const __half2*)&u.y);
                    acc[0] = fmaf(wj, f0.x, acc[0]);
                    acc[1] = fmaf(wj, f0.y, acc[1]);
                    acc[2] = fmaf(wj, f1.x, acc[2]);
                    acc[3] = fmaf(wj, f1.y, acc[3]);
                } else {
                    uint32_t u = *(const uint32_t*)srow;
                    float2 f0 = __half22float2(*(const __half2*)&u);
                    acc[0] = fmaf(wj, f0.x, acc[0]);
                    acc[1] = fmaf(wj, f0.y, acc[1]);
                }
            }
        }
    }

    float* orow = out + (size_t)node * OUT + lane * V;
    #pragma unroll
    for (int i = 0; i < V; i++) orow[i] = fmaxf(acc[i], 0.f);
}

// ======================= launch =======================
extern "C" void kernel_launch(void* const* d_in, const int* in_sizes, int n_in,
                              void* d_out, int out_size)
{
    const float* x    = (const float*)d_in[0];
    const int*   er   = (const int*)d_in[1];
    const int*   ec   = (const int*)d_in[2];
    const float* ev   = (const float*)d_in[3];
    const float* fc1w = (const float*)d_in[4];
    const float* fc1b = (const float*)d_in[5];
    const float* fc2w = (const float*)d_in[6];
    const float* fc2b = (const float*)d_in[7];
    const float* lng  = (const float*)d_in[8];
    const float* lnb  = (const float*)d_in[9];
    const float *wn[4], *wsf[4], *gb[4];
    for (int i = 0; i < 4; i++) {
        wn[i]  = (const float*)d_in[10 + 3 * i];
        wsf[i] = (const float*)d_in[11 + 3 * i];
        gb[i]  = (const float*)d_in[12 + 3 * i];
    }
    float* outp = (float*)d_out;

    float *h0, *h1, *selfb;
    __half* supn;
    __nv_bfloat16* wt;
    cudaGetSymbolAddress((void**)&h0,    g_h0);
    cudaGetSymbolAddress((void**)&h1,    g_h1);
    cudaGetSymbolAddress((void**)&supn,  g_supn);
    cudaGetSymbolAddress((void**)&selfb, g_self);
    cudaGetSymbolAddress((void**)&wt,    g_wt);
    auto WT = [&](int t) { return wt + (size_t)t * 128 * LDAB; };

    const int SMEM = A_BYTES;
    cudaFuncSetAttribute(k_mm, cudaFuncAttributeMaxDynamicSharedMemorySize, SMEM);

    const int MT = (N_NODES + 127) / 128;   // 782

    k_wprep<<<dim3(128, 9), 128>>>(fc1w, fc2w, wn[0], wsf[0], wn[1], wsf[1],
                                   wn[2], wsf[2], wn[3], wsf[3], wt);
    k_zero_rowptr<<<(NP1 + 255) / 256, 256>>>();
    k_hist<<<(N_EDGES + 255) / 256, 256>>>(er);
    k_scan1<<<NSCAN_BLOCKS, 1024>>>();
    k_scan2<<<1, 1>>>();
    k_mm<<<MT, 256, SMEM>>>(x, WT(0), fc1b, h0, 0, nullptr, 0, 1);
    k_scan3<<<NSCAN_BLOCKS, 1024>>>();
    k_copy_pos<<<(N_NODES + 255) / 256, 256>>>();
    k_fill<<<(N_EDGES + 255) / 256, 256>>>(er, ec, ev);
    k_mm<<<MT, 256, SMEM>>>(h0, WT(1), fc2b, h1, 0, nullptr, 0, 1);
    k_ln<<<N_NODES / 8, 256>>>(h1, h0, lng, lnb);

    float* cur = h0;
    float* nxt = h1;
    for (int l = 0; l < 3; l++) {
        k_mm<<<MT, 256, SMEM>>>(cur, WT(2 + 2 * l), nullptr, supn, 1, selfb, 2, 2);
        k_agg<128><<<N_NODES / 8, 256>>>(supn, selfb, gb[l], nxt);
        float* t = cur; cur = nxt; nxt = t;
    }

    k_mm<<<MT, 256, SMEM>>>(cur, WT(8), nullptr, supn, 3, selfb, 3, 1);
    k_agg<64><<<N_NODES / 8, 256>>>(supn, selfb, gb[3], outp);
}

// round 6
// speedup vs baseline: 1.7437x; 1.0449x over previous
#include <cuda_runtime.h>
#include <cuda_bf16.h>
#include <cuda_fp16.h>
#include <math.h>
#include <stdint.h>

#define N_NODES 100000
#define NPAD    100096
#define N_EDGES 3200000
#define NP1     100001
#define NSCAN_BLOCKS 98

#define LDAB 264                     // A smem row: [hi 0..127 | lo 128..255 | pad]
#define A_BYTES (128 * LDAB * 2)     // 67584
#define WT_TILE_BYTES 65536          // packed B tile: 16 nb x 8 ks x 512B

// ======================= device scratch =======================
__device__ int    g_rowptr[NP1];
__device__ int    g_bsum[128];
__device__ int    g_pos[N_NODES];
__device__ int    g_ecol[N_EDGES];
__device__ float  g_eval[N_EDGES];
__device__ float  g_h0[(size_t)NPAD * 128];
__device__ float  g_h1[(size_t)NPAD * 128];
__device__ __half g_supn[(size_t)NPAD * 128];
__device__ float  g_self[(size_t)NPAD * 128];
__device__ __nv_bfloat16 g_wt[9 * 32768];   // 9 x 64KB packed tiles

// ======================= helpers =======================
__device__ __forceinline__ uint32_t smem_u32(const void* p) {
    uint32_t a;
    asm("{ .reg .u64 t; cvta.to.shared.u64 t, %1; cvt.u32.u64 %0, t; }" : "=r"(a) : "l"(p));
    return a;
}
__device__ __forceinline__ void ldsm_x4(unsigned* r, uint32_t addr) {
    asm volatile("ldmatrix.sync.aligned.m8n8.x4.shared.b16 {%0,%1,%2,%3}, [%4];"
        : "=r"(r[0]), "=r"(r[1]), "=r"(r[2]), "=r"(r[3]) : "r"(addr));
}
__device__ __forceinline__ void mma_bf16(float* c, const unsigned* a, unsigned b0, unsigned b1) {
    asm volatile("mma.sync.aligned.m16n8k16.row.col.f32.bf16.bf16.f32 "
        "{%0,%1,%2,%3}, {%4,%5,%6,%7}, {%8,%9}, {%0,%1,%2,%3};"
        : "+f"(c[0]), "+f"(c[1]), "+f"(c[2]), "+f"(c[3])
        : "r"(a[0]), "r"(a[1]), "r"(a[2]), "r"(a[3]), "r"(b0), "r"(b1));
}

// ======================= CSR build =======================
__global__ void k_zero_rowptr() {
    int i = blockIdx.x * blockDim.x + threadIdx.x;
    if (i < NP1) g_rowptr[i] = 0;
}
__global__ void k_hist(const int* __restrict__ rows) {
    int e = blockIdx.x * blockDim.x + threadIdx.x;
    if (e < N_EDGES) atomicAdd(&g_rowptr[rows[e] + 1], 1);
}
__global__ void k_scan1() {
    __shared__ int s[1024];
    int t = threadIdx.x, i = blockIdx.x * 1024 + t;
    int v = (i < NP1) ? g_rowptr[i] : 0;
    s[t] = v; __syncthreads();
    #pragma unroll
    for (int off = 1; off < 1024; off <<= 1) {
        int tv = 0;
        if (t >= off) tv = s[t - off];
        __syncthreads(); s[t] += tv; __syncthreads();
    }
    if (i < NP1) g_rowptr[i] = s[t];
    if (t == 1023) g_bsum[blockIdx.x] = s[1023];
}
__global__ void k_scan2() {
    int acc = 0;
    for (int b = 0; b < NSCAN_BLOCKS; b++) { acc += g_bsum[b]; g_bsum[b] = acc; }
}
__global__ void k_scan3() {   // also writes g_pos
    int b = blockIdx.x;
    int i = b * 1024 + threadIdx.x;
    int add = b ? g_bsum[b - 1] : 0;
    if (i < NP1) {
        int v = g_rowptr[i] + add;
        g_rowptr[i] = v;
        if (i < N_NODES) g_pos[i] = v;
    }
}
__global__ void k_fill(const int* __restrict__ rows, const int* __restrict__ cols,
                       const float* __restrict__ vals) {
    int e = blockIdx.x * blockDim.x + threadIdx.x;
    if (e >= N_EDGES) return;
    int r = rows[e];
    int p = atomicAdd(&g_pos[r], 1);
    g_ecol[p] = cols[e];
    g_eval[p] = vals[e];
}

// ======================= weight prep: pack B in mma-fragment order ==============
// Tile layout (64KB): for nb in [0,16), ks in [0,8): 512B block =
//   for n7 in [0,8): 64B = for q in [0,4): [hi: k={2q,2q+1,2q+8,2q+9}] (8B) [lo: same] (8B)
__global__ void k_wprep(const float* __restrict__ fc1w, const float* __restrict__ fc2w,
                        const float* __restrict__ w0n, const float* __restrict__ w0s,
                        const float* __restrict__ w1n, const float* __restrict__ w1s,
                        const float* __restrict__ w2n, const float* __restrict__ w2s,
                        const float* __restrict__ w3n, const float* __restrict__ w3s,
                        __nv_bfloat16* __restrict__ wt)
{
    int t = blockIdx.y, n = blockIdx.x, k = threadIdx.x;
    float v;
    switch (t) {
        case 0: v = fc1w[n * 128 + k]; break;
        case 1: v = fc2w[n * 128 + k]; break;
        case 2: v = w0n[k * 128 + n]; break;
        case 3: v = w0s[k * 128 + n]; break;
        case 4: v = w1n[k * 128 + n]; break;
        case 5: v = w1s[k * 128 + n]; break;
        case 6: v = w2n[k * 128 + n]; break;
        case 7: v = w2s[k * 128 + n]; break;
        default: v = (n < 64) ? w3n[k * 64 + n] : w3s[k * 64 + (n - 64)]; break;
    }
    __nv_bfloat16 hi = __float2bfloat16_rn(v);
    __nv_bfloat16 lo = __float2bfloat16_rn(v - __bfloat162float(hi));

    int ks = k >> 4, kk = k & 15;
    int q, e;
    if (kk < 8) { q = kk >> 1; e = kk & 1; }
    else        { q = (kk - 8) >> 1; e = 2 + (kk & 1); }
    int nb = n >> 3, n7 = n & 7;
    char* base = (char*)wt + (size_t)t * WT_TILE_BYTES
               + ((nb * 8 + ks) * 512) + n7 * 64 + q * 16;
    *(__nv_bfloat16*)(base + e * 2)     = hi;
    *(__nv_bfloat16*)(base + 8 + e * 2) = lo;
}

// ======================= mma.sync bf16 GEMM (3-term hi/lo) =======================
// D[128, nH*128] = X[128,128] @ W^T. smem: A only. B: packed global (16B/lane frag).
// modes: 0 = f32 bias+relu (ld128); 1 = fp16 (ld128); 2 = f32 raw (ld128);
//        3 = split64: wn<2 -> fp16 o0 (ld64), wn>=2 -> f32 o1 (ld64)
__global__ __launch_bounds__(256, 2) void k_mm(
    const float* __restrict__ X,
    const __nv_bfloat16* __restrict__ Bw,
    const float* __restrict__ bias,
    void* __restrict__ o0, int m0,
    void* __restrict__ o1, int m1,
    int nH)
{
    extern __shared__ __nv_bfloat16 As[];   // 128 x LDAB

    const int tid = threadIdx.x, wid = tid >> 5, lane = tid & 31;
    const int wm = wid >> 2, wn = wid & 3;   // warp tile: 64 rows x 32 cols
    const int row0 = blockIdx.x * 128;

    // ---- load A tile, split fp32 -> bf16 hi/lo ----
    #pragma unroll
    for (int it = 0; it < 16; it++) {
        int idx = tid + 256 * it;
        int r = idx >> 5, c4 = idx & 31;
        float4 v = make_float4(0.f, 0.f, 0.f, 0.f);
        int row = row0 + r;
        if (row < N_NODES) v = *(const float4*)&X[(size_t)row * 128 + c4 * 4];
        __nv_bfloat16 hx = __float2bfloat16_rn(v.x);
        __nv_bfloat16 hy = __float2bfloat16_rn(v.y);
        __nv_bfloat16 hz = __float2bfloat16_rn(v.z);
        __nv_bfloat16 hw = __float2bfloat16_rn(v.w);
        __nv_bfloat16 lx = __float2bfloat16_rn(v.x - __bfloat162float(hx));
        __nv_bfloat16 ly = __float2bfloat16_rn(v.y - __bfloat162float(hy));
        __nv_bfloat16 lz = __float2bfloat16_rn(v.z - __bfloat162float(hz));
        __nv_bfloat16 lw = __float2bfloat16_rn(v.w - __bfloat162float(hw));
        __nv_bfloat16* ap = As + r * LDAB + c4 * 4;
        *(__nv_bfloat162*)(ap + 0)   = __halves2bfloat162(hx, hy);
        *(__nv_bfloat162*)(ap + 2)   = __halves2bfloat162(hz, hw);
        *(__nv_bfloat162*)(ap + 128) = __halves2bfloat162(lx, ly);
        *(__nv_bfloat162*)(ap + 130) = __halves2bfloat162(lz, lw);
    }
    __syncthreads();

    const uint32_t aBase = smem_u32(As) +
        2u * (uint32_t)((wm * 64 + (lane & 15)) * LDAB + ((lane >> 4) << 3));
    // per-lane packed-B base: n7 = lane>>2, q = lane&3
    const char* bLane = (const char*)Bw + (lane >> 2) * 64 + (lane & 3) * 16;

    for (int nh = 0; nh < nH; nh++) {
        const char* Bt = bLane + (size_t)nh * WT_TILE_BYTES;

        float acc[4][4][4];
        #pragma unroll
        for (int i = 0; i < 4; i++)
            #pragma unroll
            for (int j = 0; j < 4; j++)
                #pragma unroll
                for (int q = 0; q < 4; q++) acc[i][j][q] = 0.f;

        #pragma unroll
        for (int ks = 0; ks < 8; ks++) {
            const int ka = ks * 16;
            uint4 bv[4];
            #pragma unroll
            for (int j = 0; j < 4; j++)
                bv[j] = *(const uint4*)(Bt + ((wn * 4 + j) * 8 + ks) * 512);

            unsigned ah[4][4];
            #pragma unroll
            for (int i = 0; i < 4; i++)
                ldsm_x4(ah[i], aBase + 2u * (uint32_t)(i * 16 * LDAB + ka));
            #pragma unroll
            for (int i = 0; i < 4; i++)
                #pragma unroll
                for (int j = 0; j < 4; j++)
                    mma_bf16(acc[i][j], ah[i], bv[j].x, bv[j].y);   // Ah x Bh
            {
                unsigned al[4][4];
                #pragma unroll
                for (int i = 0; i < 4; i++)
                    ldsm_x4(al[i], aBase + 2u * (uint32_t)(i * 16 * LDAB + ka + 128));
                #pragma unroll
                for (int i = 0; i < 4; i++)
                    #pragma unroll
                    for (int j = 0; j < 4; j++)
                        mma_bf16(acc[i][j], al[i], bv[j].x, bv[j].y);   // Al x Bh
            }
            #pragma unroll
            for (int i = 0; i < 4; i++)
                #pragma unroll
                for (int j = 0; j < 4; j++)
                    mma_bf16(acc[i][j], ah[i], bv[j].z, bv[j].w);   // Ah x Bl
        }

        // ---- register epilogue (outputs NPAD-padded: no row guard) ----
        const int mode = (nh == 0) ? m0 : m1;
        const int cb = wn * 32 + 2 * (lane & 3);
        const int rb = row0 + wm * 64 + (lane >> 2);

        if (mode == 0) {
            float2 bvv[4];
            #pragma unroll
            for (int j = 0; j < 4; j++) bvv[j] = *(const float2*)&bias[cb + j * 8];
            float* out = (float*)o0;
            #pragma unroll
            for (int i = 0; i < 4; i++) {
                size_t r1 = (size_t)(rb + i * 16) * 128;
                size_t r2 = r1 + 8 * 128;
                #pragma unroll
                for (int j = 0; j < 4; j++) {
                    float* a = acc[i][j];
                    int c = cb + j * 8;
                    *(float2*)&out[r1 + c] = make_float2(fmaxf(a[0] + bvv[j].x, 0.f),
                                                         fmaxf(a[1] + bvv[j].y, 0.f));
                    *(float2*)&out[r2 + c] = make_float2(fmaxf(a[2] + bvv[j].x, 0.f),
                                                         fmaxf(a[3] + bvv[j].y, 0.f));
                }
            }
        } else if (mode == 1) {
            __half* out = (__half*)o0;
            #pragma unroll
            for (int i = 0; i < 4; i++) {
                size_t r1 = (size_t)(rb + i * 16) * 128;
                size_t r2 = r1 + 8 * 128;
                #pragma unroll
                for (int j = 0; j < 4; j++) {
                    float* a = acc[i][j];
                    int c = cb + j * 8;
                    *(__half2*)&out[r1 + c] = __floats2half2_rn(a[0], a[1]);
                    *(__half2*)&out[r2 + c] = __floats2half2_rn(a[2], a[3]);
                }
            }
        } else if (mode == 2) {
            float* out = (float*)o1;
            #pragma unroll
            for (int i = 0; i < 4; i++) {
                size_t r1 = (size_t)(rb + i * 16) * 128;
                size_t r2 = r1 + 8 * 128;
                #pragma unroll
                for (int j = 0; j < 4; j++) {
                    float* a = acc[i][j];
                    int c = cb + j * 8;
                    *(float2*)&out[r1 + c] = make_float2(a[0], a[1]);
                    *(float2*)&out[r2 + c] = make_float2(a[2], a[3]);
                }
            }
        } else {   // mode 3: cols<64 -> fp16 o0 (ld64); cols>=64 -> f32 o1 (ld64)
            if (wn < 2) {
                __half* out = (__half*)o0;
                #pragma unroll
                for (int i = 0; i < 4; i++) {
                    size_t r1 = (size_t)(rb + i * 16) * 64;
                    size_t r2 = r1 + 8 * 64;
                    #pragma unroll
                    for (int j = 0; j < 4; j++) {
                        float* a = acc[i][j];
                        int c = cb + j * 8;
                        *(__half2*)&out[r1 + c] = __floats2half2_rn(a[0], a[1]);
                        *(__half2*)&out[r2 + c] = __floats2half2_rn(a[2], a[3]);
                    }
                }
            } else {
                float* out = (float*)o1;
                #pragma unroll
                for (int i = 0; i < 4; i++) {
                    size_t r1 = (size_t)(rb + i * 16) * 64;
                    size_t r2 = r1 + 8 * 64;
                    #pragma unroll
                    for (int j = 0; j < 4; j++) {
                        float* a = acc[i][j];
                        int c = cb + j * 8 - 64;
                        *(float2*)&out[r1 + c] = make_float2(a[0], a[1]);
                        *(float2*)&out[r2 + c] = make_float2(a[2], a[3]);
                    }
                }
            }
        }
    }
}

// ======================= LayerNorm =======================
__global__ __launch_bounds__(256) void k_ln(const float* __restrict__ in,
                                            float* __restrict__ out,
                                            const float* __restrict__ g,
                                            const float* __restrict__ b)
{
    int row  = blockIdx.x * 8 + (threadIdx.x >> 5);
    int lane = threadIdx.x & 31;
    float4 v = *(const float4*)&in[(size_t)row * 128 + lane * 4];
    float s = v.x + v.y + v.z + v.w;
    #pragma unroll
    for (int o = 16; o; o >>= 1) s += __shfl_xor_sync(0xffffffffu, s, o);
    float mean = s * (1.f / 128.f);
    float dx = v.x - mean, dy = v.y - mean, dz = v.z - mean, dw = v.w - mean;
    float ss = dx*dx + dy*dy + dz*dz + dw*dw;
    #pragma unroll
    for (int o = 16; o; o >>= 1) ss += __shfl_xor_sync(0xffffffffu, ss, o);
    float inv = 1.f / (sqrtf(ss * (1.f / 127.f)) + 1e-6f);
    float4 gg = *(const float4*)&g[lane * 4];
    float4 bb = *(const float4*)&b[lane * 4];
    float4 o4;
    o4.x = gg.x * dx * inv + bb.x;
    o4.y = gg.y * dy * inv + bb.y;
    o4.z = gg.z * dz * inv + bb.z;
    o4.w = gg.w * dw * inv + bb.w;
    *(float4*)&out[(size_t)row * 128 + lane * 4] = o4;
}

// ======================= GCN aggregate (fp16 gather) =======================
template <int OUT>
__global__ __launch_bounds__(256) void k_agg(const __half* __restrict__ supn,
                                             const float* __restrict__ selfm,
                                             const float* __restrict__ bias,
                                             float* __restrict__ out)
{
    const int V = OUT / 32;
    int node = blockIdx.x * 8 + (threadIdx.x >> 5);
    int lane = threadIdx.x & 31;

    float acc[V];
    {
        const float* sr = selfm + (size_t)node * OUT + lane * V;
        #pragma unroll
        for (int i = 0; i < V; i++) acc[i] = sr[i] + bias[lane * V + i];
    }

    int e0 = g_rowptr[node], e1 = g_rowptr[node + 1];
    for (int eb = e0; eb < e1; eb += 32) {
        int rem = e1 - eb;
        int c = 0; float wv = 0.f;
        if (lane < rem) { c = g_ecol[eb + lane]; wv = g_eval[eb + lane]; }
        if (rem >= 32) {
            #pragma unroll 8
            for (int j = 0; j < 32; j++) {
                int   cj = __shfl_sync(0xffffffffu, c, j);
                float wj = __shfl_sync(0xffffffffu, wv, j);
                const __half* srow = supn + (size_t)cj * OUT + lane * V;
                if (V == 4) {
                    uint2 u = *(const uint2*)srow;
                    float2 f0 = __half22float2(*(const __half2*)&u.x);
                    float2 f1 = __half22float2(*(const __half2*)&u.y);
                    acc[0] = fmaf(wj, f0.x, acc[0]);
                    acc[1] = fmaf(wj, f0.y, acc[1]);
                    acc[2] = fmaf(wj, f1.x, acc[2]);
                    acc[3] = fmaf(wj, f1.y, acc[3]);
                } else {
                    uint32_t u = *(const uint32_t*)srow;
                    float2 f0 = __half22float2(*(const __half2*)&u);
                    acc[0] = fmaf(wj, f0.x, acc[0]);
                    acc[1] = fmaf(wj, f0.y, acc[1]);
                }
            }
        } else {
            for (int j = 0; j < rem; j++) {
                int   cj = __shfl_sync(0xffffffffu, c, j);
                float wj = __shfl_sync(0xffffffffu, wv, j);
                const __half* srow = supn + (size_t)cj * OUT + lane * V;
                if (V == 4) {
                    uint2 u = *(const uint2*)srow;
                    float2 f0 = __half22float2(*(const __half2*)&u.x);
                    float2 f1 = __half22float2(*(const __half2*)&u.y);
                    acc[0] = fmaf(wj, f0.x, acc[0]);
                    acc[1] = fmaf(wj, f0.y, acc[1]);
                    acc[2] = fmaf(wj, f1.x, acc[2]);
                    acc[3] = fmaf(wj, f1.y, acc[3]);
                } else {
                    uint32_t u = *(const uint32_t*)srow;
                    float2 f0 = __half22float2(*(const __half2*)&u);
                    acc[0] = fmaf(wj, f0.x, acc[0]);
                    acc[1] = fmaf(wj, f0.y, acc[1]);
                }
            }
        }
    }

    float* orow = out + (size_t)node * OUT + lane * V;
    #pragma unroll
    for (int i = 0; i < V; i++) orow[i] = fmaxf(acc[i], 0.f);
}

// ======================= launch =======================
extern "C" void kernel_launch(void* const* d_in, const int* in_sizes, int n_in,
                              void* d_out, int out_size)
{
    const float* x    = (const float*)d_in[0];
    const int*   er   = (const int*)d_in[1];
    const int*   ec   = (const int*)d_in[2];
    const float* ev   = (const float*)d_in[3];
    const float* fc1w = (const float*)d_in[4];
    const float* fc1b = (const float*)d_in[5];
    const float* fc2w = (const float*)d_in[6];
    const float* fc2b = (const float*)d_in[7];
    const float* lng  = (const float*)d_in[8];
    const float* lnb  = (const float*)d_in[9];
    const float *wn[4], *wsf[4], *gb[4];
    for (int i = 0; i < 4; i++) {
        wn[i]  = (const float*)d_in[10 + 3 * i];
        wsf[i] = (const float*)d_in[11 + 3 * i];
        gb[i]  = (const float*)d_in[12 + 3 * i];
    }
    float* outp = (float*)d_out;

    float *h0, *h1, *selfb;
    __half* supn;
    __nv_bfloat16* wt;
    cudaGetSymbolAddress((void**)&h0,    g_h0);
    cudaGetSymbolAddress((void**)&h1,    g_h1);
    cudaGetSymbolAddress((void**)&supn,  g_supn);
    cudaGetSymbolAddress((void**)&selfb, g_self);
    cudaGetSymbolAddress((void**)&wt,    g_wt);
    auto WT = [&](int t) { return wt + (size_t)t * 32768; };

    const int SMEM = A_BYTES;
    cudaFuncSetAttribute(k_mm, cudaFuncAttributeMaxDynamicSharedMemorySize, SMEM);

    const int MT = (N_NODES + 127) / 128;   // 782

    k_wprep<<<dim3(128, 9), 128>>>(fc1w, fc2w, wn[0], wsf[0], wn[1], wsf[1],
                                   wn[2], wsf[2], wn[3], wsf[3], wt);           // 0
    k_zero_rowptr<<<(NP1 + 255) / 256, 256>>>();                                 // 1
    k_hist<<<(N_EDGES + 255) / 256, 256>>>(er);                                  // 2
    k_mm<<<MT, 256, SMEM>>>(x, WT(0), fc1b, h0, 0, nullptr, 0, 1);               // 3 <- profiled
    k_scan1<<<NSCAN_BLOCKS, 1024>>>();                                           // 4
    k_scan2<<<1, 1>>>();                                                         // 5
    k_scan3<<<NSCAN_BLOCKS, 1024>>>();                                           // 6
    k_fill<<<(N_EDGES + 255) / 256, 256>>>(er, ec, ev);                          // 7
    k_mm<<<MT, 256, SMEM>>>(h0, WT(1), fc2b, h1, 0, nullptr, 0, 1);              // 8
    k_ln<<<N_NODES / 8, 256>>>(h1, h0, lng, lnb);                                // 9

    float* cur = h0;
    float* nxt = h1;
    for (int l = 0; l < 3; l++) {
        k_mm<<<MT, 256, SMEM>>>(cur, WT(2 + 2 * l), nullptr, supn, 1, selfb, 2, 2);
        k_agg<128><<<N_NODES / 8, 256>>>(supn, selfb, gb[l], nxt);
        float* t = cur; cur = nxt; nxt = t;
    }

    k_mm<<<MT, 256, SMEM>>>(cur, WT(8), nullptr, supn, 3, selfb, 3, 1);
    k_agg<64><<<N_NODES / 8, 256>>>(supn, selfb, gb[3], outp);
}